// round 5
// baseline (speedup 1.0000x reference)
#include <cuda_runtime.h>
#include <math_constants.h>

#define NROWS 2048
#define DIM   1024
#define KCENT 256
#define NB    1024
#define RPB   4            // rows per CTA (one warp per row)
#define MTPB  128
#define MGRID (NROWS / RPB)

__device__ float2 g_tab[KCENT];   // (midpoint, centroid); mid[255] = +inf
__device__ int    g_lut[NB];      // lower-bound index per uniform bin
__device__ float  g_sb[2];        // scale, bias

// ---------------- prep: build tables once ----------------
__global__ __launch_bounds__(256)
void prep_kernel(const float* __restrict__ centroids) {
    __shared__ float smid[KCENT];
    __shared__ int   lut[NB];
    __shared__ int   swsum[8];

    const int t    = threadIdx.x;
    const int lane = t & 31;
    const int wid  = t >> 5;

    const float c0 = centroids[t];
    const float c1 = centroids[t < KCENT - 1 ? t + 1 : KCENT - 1];
    const float mid = (t < KCENT - 1) ? 0.5f * (c0 + c1) : CUDART_INF_F;
    smid[t] = mid;
    g_tab[t] = make_float2(mid, c0);
    reinterpret_cast<int4*>(lut)[t] = make_int4(0, 0, 0, 0);
    __syncthreads();

    const float lo    = smid[0];
    const float hi    = smid[KCENT - 2];
    const float scale = (float)NB / fmaxf(hi - lo, 1e-30f);
    const float bias  = -lo * scale;
    if (t == 0) { g_sb[0] = scale; g_sb[1] = bias; }

    if (t < KCENT - 1) {
        float bf = fmaf(mid, scale, bias);
        int b = (int)fminf(fmaxf(bf, 0.0f), (float)(NB - 1));
        atomicAdd(&lut[b], 1);
    }
    __syncthreads();

    // exclusive prefix scan over NB bins (4 bins/thread)
    int4 h = reinterpret_cast<int4*>(lut)[t];
    const int hsum = h.x + h.y + h.z + h.w;
    int inc = hsum;
    #pragma unroll
    for (int o = 1; o < 32; o <<= 1) {
        int n = __shfl_up_sync(0xffffffffu, inc, o);
        if (lane >= o) inc += n;
    }
    if (lane == 31) swsum[wid] = inc;
    __syncthreads();

    int base = inc - hsum;
    #pragma unroll
    for (int i = 0; i < 8; i++)
        if (i < wid) base += swsum[i];

    int4 e;
    e.x = base;
    e.y = e.x + h.x;  e.z = e.y + h.y;  e.w = e.z + h.z;
    reinterpret_cast<int4*>(g_lut)[t] = e;
}

// ---------------- main: warp-per-row ----------------
__global__ __launch_bounds__(MTPB)
void planar_quant_kernel(const float* __restrict__ x,
                         const float* __restrict__ rot2,
                         float* __restrict__ out_xhat,
                         float* __restrict__ out_idx,
                         int write_idx) {
    __shared__ float2 tab[KCENT];
    __shared__ int    lut[NB];

    const int t    = threadIdx.x;
    const int lane = t & 31;
    const int wid  = t >> 5;

    // copy tables to smem: lut = 256 int4, tab = 128 float4 -> 3 vec loads/thread
    reinterpret_cast<int4*>(lut)[t]         = reinterpret_cast<const int4*>(g_lut)[t];
    reinterpret_cast<int4*>(lut)[t + MTPB]  = reinterpret_cast<const int4*>(g_lut)[t + MTPB];
    reinterpret_cast<float4*>(tab)[t]       = reinterpret_cast<const float4*>(g_tab)[t];
    const float scale = g_sb[0];
    const float bias  = g_sb[1];

    const int row = blockIdx.x * RPB + wid;
    const float4* __restrict__ xrow = reinterpret_cast<const float4*>(x) + (size_t)row * (DIM / 4);
    const float4* __restrict__ rv4  = reinterpret_cast<const float4*>(rot2);

    // pass 1: sum of squares (warp-local, no barrier)
    float ss = 0.f;
    #pragma unroll
    for (int k = 0; k < 8; k++) {
        float4 v = xrow[k * 32 + lane];
        ss += v.x * v.x + v.y * v.y + v.z * v.z + v.w * v.w;
    }
    #pragma unroll
    for (int o = 16; o; o >>= 1) ss += __shfl_xor_sync(0xffffffffu, ss, o);

    const float norm = fmaxf(sqrtf(ss), 1e-8f);
    const float rn   = 1.0f / norm;

    __syncthreads();   // tables visible (overlapped with pass-1 DRAM latency)

    auto quant = [&](float v, int& idx, float& q) {
        float bf = fmaf(v, scale, bias);
        int b = (int)fminf(fmaxf(bf, 0.0f), (float)(NB - 1));
        int i = lut[b];
        float2 tc = tab[i];
        if (tc.x < v) { i++; tc = tab[i]; }
        if (tc.x < v) { i++; tc = tab[i]; }
        while (tc.x < v) { i++; tc = tab[i]; }   // rare; mid[255]=+inf terminates
        idx = i; q = tc.y;
    };

    float4* __restrict__ orow = reinterpret_cast<float4*>(out_xhat) + (size_t)row * (DIM / 4);
    float4* __restrict__ irow = reinterpret_cast<float4*>(out_idx)  + (size_t)row * (DIM / 4);

    // pass 2: rotate -> quantize -> inverse rotate -> store (x reload is L1-hot)
    #pragma unroll
    for (int k = 0; k < 8; k++) {
        const float4 xv = xrow[k * 32 + lane];
        const float4 rv = rv4[k * 32 + lane];

        const float v0 = xv.x * rn, v1 = xv.y * rn;
        const float v2 = xv.z * rn, v3 = xv.w * rn;
        const float r0 = rv.x * v0 - rv.y * v1;
        const float r1 = rv.y * v0 + rv.x * v1;
        const float r2 = rv.z * v2 - rv.w * v3;
        const float r3 = rv.w * v2 + rv.z * v3;

        int   i0, i1, i2, i3;
        float q0, q1, q2, q3;
        quant(r0, i0, q0);
        quant(r1, i1, q1);
        quant(r2, i2, q2);
        quant(r3, i3, q3);

        float4 xh;
        xh.x = ( rv.x * q0 + rv.y * q1) * norm;
        xh.y = (-rv.y * q0 + rv.x * q1) * norm;
        xh.z = ( rv.z * q2 + rv.w * q3) * norm;
        xh.w = (-rv.w * q2 + rv.z * q3) * norm;
        orow[k * 32 + lane] = xh;

        if (write_idx) {
            float4 fi;
            fi.x = (float)i0; fi.y = (float)i1; fi.z = (float)i2; fi.w = (float)i3;
            irow[k * 32 + lane] = fi;
        }
    }
}

extern "C" void kernel_launch(void* const* d_in, const int* in_sizes, int n_in,
                              void* d_out, int out_size) {
    const float* x         = (const float*)d_in[0];  // [2048, 1024]
    const float* centroids = (const float*)d_in[1];  // [256]
    const float* rot2      = (const float*)d_in[2];  // [512, 2]

    float* out = (float*)d_out;
    const int full = (out_size >= 2 * NROWS * DIM);
    float* out_xhat = out;
    float* out_idx  = full ? out + (size_t)NROWS * DIM : out;

    prep_kernel<<<1, 256>>>(centroids);
    planar_quant_kernel<<<MGRID, MTPB>>>(x, rot2, out_xhat, out_idx, full);
}

// round 6
// speedup vs baseline: 1.0641x; 1.0641x over previous
#include <cuda_runtime.h>
#include <math_constants.h>

#define NROWS 2048
#define DIM   1024
#define KCENT 256
#define NB    1024
#define TPB   256

__device__ float2 g_tab[KCENT];   // (midpoint, centroid); mid[255] = +inf
__device__ int    g_lut[NB];      // lower-bound index per uniform bin
__device__ float  g_sb[2];        // scale, bias

// ---------------- prep: build tables once (1 CTA) ----------------
__global__ __launch_bounds__(256)
void prep_kernel(const float* __restrict__ centroids) {
    __shared__ float smid[KCENT];
    __shared__ int   lut[NB];
    __shared__ int   swsum[8];

    const int t    = threadIdx.x;
    const int lane = t & 31;
    const int wid  = t >> 5;

    const float c0 = centroids[t];
    const float c1 = centroids[t < KCENT - 1 ? t + 1 : KCENT - 1];
    const float mid = (t < KCENT - 1) ? 0.5f * (c0 + c1) : CUDART_INF_F;
    smid[t] = mid;
    g_tab[t] = make_float2(mid, c0);
    reinterpret_cast<int4*>(lut)[t] = make_int4(0, 0, 0, 0);
    __syncthreads();

    const float lo    = smid[0];
    const float hi    = smid[KCENT - 2];
    const float scale = (float)NB / fmaxf(hi - lo, 1e-30f);
    const float bias  = -lo * scale;
    if (t == 0) { g_sb[0] = scale; g_sb[1] = bias; }

    if (t < KCENT - 1) {
        float bf = fmaf(mid, scale, bias);
        int b = (int)fminf(fmaxf(bf, 0.0f), (float)(NB - 1));
        atomicAdd(&lut[b], 1);
    }
    __syncthreads();

    // exclusive prefix scan over NB bins (4 bins/thread)
    int4 h = reinterpret_cast<int4*>(lut)[t];
    const int hsum = h.x + h.y + h.z + h.w;
    int inc = hsum;
    #pragma unroll
    for (int o = 1; o < 32; o <<= 1) {
        int n = __shfl_up_sync(0xffffffffu, inc, o);
        if (lane >= o) inc += n;
    }
    if (lane == 31) swsum[wid] = inc;
    __syncthreads();

    int base = inc - hsum;
    #pragma unroll
    for (int i = 0; i < 8; i++)
        if (i < wid) base += swsum[i];

    int4 e;
    e.x = base;
    e.y = e.x + h.x;  e.z = e.y + h.y;  e.w = e.z + h.z;
    reinterpret_cast<int4*>(g_lut)[t] = e;
}

// ---------------- main: 1 row per CTA, 4 scalars/thread ----------------
__global__ __launch_bounds__(TPB)
void planar_quant_kernel(const float* __restrict__ x,
                         const float* __restrict__ rot2,
                         float* __restrict__ out_xhat,
                         float* __restrict__ out_idx,
                         int write_idx) {
    __shared__ float2 tab[KCENT];
    __shared__ int    lut[NB];
    __shared__ float  sred[8];

    const int t    = threadIdx.x;
    const int lane = t & 31;
    const int wid  = t >> 5;
    const int row  = blockIdx.x;

    // ---- long-latency loads first ----
    const float4 xv = reinterpret_cast<const float4*>(x + (size_t)row * DIM)[t];
    const float4 rv = reinterpret_cast<const float4*>(rot2)[t];
    const float scale = g_sb[0];
    const float bias  = g_sb[1];

    // ---- copy tables to smem: lut = 256 int4 (1/thread), tab = 128 float4 ----
    reinterpret_cast<int4*>(lut)[t] = reinterpret_cast<const int4*>(g_lut)[t];
    if (t < KCENT / 2)
        reinterpret_cast<float4*>(tab)[t] = reinterpret_cast<const float4*>(g_tab)[t];

    // ---- norm partials ----
    float ss = xv.x * xv.x + xv.y * xv.y + xv.z * xv.z + xv.w * xv.w;
    #pragma unroll
    for (int o = 16; o; o >>= 1) ss += __shfl_xor_sync(0xffffffffu, ss, o);
    if (lane == 0) sred[wid] = ss;

    __syncthreads();   // one barrier: tables + partials visible

    float4 s0 = reinterpret_cast<float4*>(sred)[0];
    float4 s1 = reinterpret_cast<float4*>(sred)[1];
    float total = (s0.x + s0.y) + (s0.z + s0.w) + (s1.x + s1.y) + (s1.z + s1.w);
    const float norm = fmaxf(sqrtf(total), 1e-8f);
    const float rn   = 1.0f / norm;

    // ---- rotate ----
    const float v0 = xv.x * rn, v1 = xv.y * rn;
    const float v2 = xv.z * rn, v3 = xv.w * rn;
    const float r0 = rv.x * v0 - rv.y * v1;
    const float r1 = rv.y * v0 + rv.x * v1;
    const float r2 = rv.z * v2 - rv.w * v3;
    const float r3 = rv.w * v2 + rv.z * v3;

    // ---- quantize: LUT lower bound + exact walk (argmin semantics) ----
    auto quant = [&](float v, int& idx, float& q) {
        float bf = fmaf(v, scale, bias);
        int b = (int)fminf(fmaxf(bf, 0.0f), (float)(NB - 1));
        int i = lut[b];
        float2 tc = tab[i];
        if (tc.x < v) { i++; tc = tab[i]; }
        if (tc.x < v) { i++; tc = tab[i]; }
        while (tc.x < v) { i++; tc = tab[i]; }   // rare; mid[255]=+inf terminates
        idx = i; q = tc.y;
    };

    int   i0, i1, i2, i3;
    float q0, q1, q2, q3;
    quant(r0, i0, q0);
    quant(r1, i1, q1);
    quant(r2, i2, q2);
    quant(r3, i3, q3);

    // ---- inverse rotate, rescale, store ----
    float4 xh;
    xh.x = ( rv.x * q0 + rv.y * q1) * norm;
    xh.y = (-rv.y * q0 + rv.x * q1) * norm;
    xh.z = ( rv.z * q2 + rv.w * q3) * norm;
    xh.w = (-rv.w * q2 + rv.z * q3) * norm;
    reinterpret_cast<float4*>(out_xhat + (size_t)row * DIM)[t] = xh;

    if (write_idx) {
        float4 fi;
        fi.x = (float)i0; fi.y = (float)i1; fi.z = (float)i2; fi.w = (float)i3;
        reinterpret_cast<float4*>(out_idx + (size_t)row * DIM)[t] = fi;
    }
}

extern "C" void kernel_launch(void* const* d_in, const int* in_sizes, int n_in,
                              void* d_out, int out_size) {
    const float* x         = (const float*)d_in[0];  // [2048, 1024]
    const float* centroids = (const float*)d_in[1];  // [256]
    const float* rot2      = (const float*)d_in[2];  // [512, 2]

    float* out = (float*)d_out;
    const int full = (out_size >= 2 * NROWS * DIM);
    float* out_xhat = out;
    float* out_idx  = full ? out + (size_t)NROWS * DIM : out;

    prep_kernel<<<1, 256>>>(centroids);
    planar_quant_kernel<<<NROWS, TPB>>>(x, rot2, out_xhat, out_idx, full);
}